// round 12
// baseline (speedup 1.0000x reference)
#include <cuda_runtime.h>
#include <math.h>

#define NPTS 262144
#define NLVL 16
#define TSZ  (1u << 19)
#define TMASK (TSZ - 1u)

// ---------------------------------------------------------------------------
constexpr int OFF_SW0 = 0;            // 32*64
constexpr int OFF_SW1 = 2048;         // 64*64
constexpr int OFF_SW2 = 6144;         // 64*16
constexpr int OFF_CW0 = 7168;         // 42*64
constexpr int OFF_CW1 = 9856;         // 64*64
constexpr int OFF_CW2 = 13952;        // 64*3
constexpr int W_TOTAL = 14144;
__constant__ float c_w[W_TOTAL];

__constant__ int c_res[NLVL] = {16, 20, 25, 32, 40, 50, 64, 80,
                                101, 128, 161, 203, 256, 322, 406, 512};

constexpr int BP = 128;
constexpr int NT = 512;               // threads per CTA
constexpr int S  = 132;
constexpr int OFF_B0 = 0;
constexpr int OFF_B1 = 64 * S;
constexpr int SMEM_FLOATS = 2 * 64 * S;          // 16896
constexpr int SMEM_BYTES  = SMEM_FLOATS * 4;     // 67584

// ---------------------------------------------------------------------------
// GEMM: y[64][S] = act(W[IN][64]^T x[IN][S]).
// warp -> 16 neurons x 32 points (4 n-groups x 4 p-groups = 16 warps).
// lane -> 1 point: LDS.32 = 1 wavefront per input row.
// Weights are warp-uniform -> uniform const port (LDCU), FFMA w/ UR operand.
// ---------------------------------------------------------------------------
template <int IN, bool RELU>
__device__ __forceinline__ void gemmS(const float* __restrict__ xb,
                                      float* __restrict__ yb,
                                      int woff, int warp, int lane)
{
    const int ng = warp & 3;           // neuron group (16 neurons)
    const int pg = warp >> 2;          // point group (32 points)
    float acc[16];
    #pragma unroll
    for (int n = 0; n < 16; n++) acc[n] = 0.f;

    const float* xr = xb + pg * 32 + lane;
    const float* wr = c_w + woff + ng * 16;
    #pragma unroll 4
    for (int i = 0; i < IN; i++) {
        float xv = xr[i * S];                       // LDS.32, 1 wavefront
        #pragma unroll
        for (int n = 0; n < 16; n++)
            acc[n] = fmaf(xv, wr[i * 64 + n], acc[n]);  // uniform weight
    }
    #pragma unroll
    for (int n = 0; n < 16; n++) {
        float v = RELU ? fmaxf(acc[n], 0.f) : acc[n];
        yb[(ng * 16 + n) * S + pg * 32 + lane] = v;  // STS.32, 1 wavefront
    }
}

// sw2 (64 -> 16): 4 warps, warp -> 16 neurons x 32 points
__device__ __forceinline__ void gemm16S(const float* __restrict__ xb,
                                        float* __restrict__ yb,
                                        int warp, int lane)
{
    const int pg = warp;               // 0..3
    float acc[16];
    #pragma unroll
    for (int n = 0; n < 16; n++) acc[n] = 0.f;

    const float* xr = xb + pg * 32 + lane;
    const float* wr = c_w + OFF_SW2;
    #pragma unroll 4
    for (int i = 0; i < 64; i++) {
        float xv = xr[i * S];
        #pragma unroll
        for (int n = 0; n < 16; n++)
            acc[n] = fmaf(xv, wr[i * 16 + n], acc[n]);
    }
    #pragma unroll
    for (int n = 0; n < 16; n++)
        yb[n * S + pg * 32 + lane] = acc[n];
}

// ---------------------------------------------------------------------------
// Fused kernel: hash encode (-> smem) then MLPs. 128 points / block, 512 thr.
// ---------------------------------------------------------------------------
__global__ __launch_bounds__(NT, 2) void fused_kernel(
    const float* __restrict__ xyzt,
    const float* __restrict__ dirs,
    const float* __restrict__ table,
    float* __restrict__ out)
{
    extern __shared__ float s[];
    const int tid = threadIdx.x;
    const int warp = tid >> 5, lane = tid & 31;
    const int gbase = blockIdx.x * BP;

    // ---- stage xyzt into B1 (512 floats) ----
    if (tid < 512)
        s[OFF_B1 + tid] = xyzt[(size_t)gbase * 4 + tid];
    __syncthreads();

    // ---- hash phase: 4 threads per point, 4 levels each (R10-validated) ----
    {
        const int p = tid & 127;
        const int lh = tid >> 7;                     // 0..3 (warp-uniform)
        float4 pt = *(const float4*)(s + OFF_B1 + p * 4);

        #pragma unroll 1
        for (int k = 0; k < 4; k++) {
            const int l = 4 * k + lh;
            float r = (float)c_res[l];
            float px = pt.x * r, py = pt.y * r, pz = pt.z * r, pw = pt.w * r;
            float fx = floorf(px), fy = floorf(py), fz = floorf(pz), ft = floorf(pw);
            float wx = px - fx, wy = py - fy, wz = pz - fz, wt = pw - ft;
            unsigned cx = (unsigned)fx, cy = (unsigned)fy,
                     cz = (unsigned)fz, ct = (unsigned)ft;

            unsigned hx0 = cx,               hx1 = cx + 1u;
            unsigned hy0 = cy * 2654435761u, hy1 = (cy + 1u) * 2654435761u;
            unsigned hz0 = cz * 805459861u,  hz1 = (cz + 1u) * 805459861u;
            unsigned ht0 = ct * 3674653429u, ht1 = (ct + 1u) * 3674653429u;

            float wx0 = 1.f - wx, wy0 = 1.f - wy, wz0 = 1.f - wz, wt0 = 1.f - wt;

            const float2* tl = (const float2*)table + (size_t)l * TSZ;
            float a0 = 0.f, a1 = 0.f;

            if ((cx & 1u) == 0u) {
                const float4* t4 = (const float4*)tl;
                #pragma unroll
                for (int c8 = 0; c8 < 8; c8++) {
                    unsigned hyy = (c8 & 1) ? hy1 : hy0;
                    unsigned hzz = (c8 & 2) ? hz1 : hz0;
                    unsigned htt = (c8 & 4) ? ht1 : ht0;
                    unsigned idx0 = (hx0 ^ hyy ^ hzz ^ htt) & TMASK;
                    float wyzt = ((c8 & 1) ? wy : wy0) * ((c8 & 2) ? wz : wz0) *
                                 ((c8 & 4) ? wt : wt0);
                    float w0 = wx0 * wyzt, w1 = wx * wyzt;
                    float4 v = __ldg(&t4[idx0 >> 1]);
                    bool hi = (idx0 & 1u);
                    float f0x = hi ? v.z : v.x, f0y = hi ? v.w : v.y;
                    float f1x = hi ? v.x : v.z, f1y = hi ? v.y : v.w;
                    a0 = fmaf(f0x, w0, a0); a0 = fmaf(f1x, w1, a0);
                    a1 = fmaf(f0y, w0, a1); a1 = fmaf(f1y, w1, a1);
                }
            } else {
                #pragma unroll
                for (int c8 = 0; c8 < 16; c8++) {
                    unsigned hxx = (c8 & 1) ? hx1 : hx0;
                    unsigned hyy = (c8 & 2) ? hy1 : hy0;
                    unsigned hzz = (c8 & 4) ? hz1 : hz0;
                    unsigned htt = (c8 & 8) ? ht1 : ht0;
                    unsigned idx = (hxx ^ hyy ^ hzz ^ htt) & TMASK;
                    float w = ((c8 & 1) ? wx : wx0) * ((c8 & 2) ? wy : wy0) *
                              ((c8 & 4) ? wz : wz0) * ((c8 & 8) ? wt : wt0);
                    float2 f = __ldg(&tl[idx]);
                    a0 = fmaf(f.x, w, a0);
                    a1 = fmaf(f.y, w, a1);
                }
            }
            s[OFF_B0 + (2 * l + 0) * S + p] = a0;
            s[OFF_B0 + (2 * l + 1) * S + p] = a1;
        }
    }
    __syncthreads();

    // ---- sigma net ----
    gemmS<32, true>(s + OFF_B0, s + OFF_B1, OFF_SW0, warp, lane);
    __syncthreads();
    gemmS<64, true>(s + OFF_B1, s + OFF_B0, OFF_SW1, warp, lane);
    __syncthreads();
    if (warp < 4)
        gemm16S(s + OFF_B0, s + OFF_B1, warp, lane);   // h -> B1 rows 0..15
    __syncthreads();

    // ---- color input assembly + sigma output ----
    if (tid < BP) {
        const int p = tid;
        const int gn = gbase + p;
        float d0 = dirs[(size_t)gn * 3 + 0];
        float d1 = dirs[(size_t)gn * 3 + 1];
        float d2 = dirs[(size_t)gn * 3 + 2];
        s[OFF_B0 + 0 * S + p] = d0;
        s[OFF_B0 + 1 * S + p] = d1;
        s[OFF_B0 + 2 * S + p] = d2;
        float dd[3] = {d0, d1, d2};
        #pragma unroll
        for (int f = 0; f < 4; f++) {
            float fr = (float)(1 << f);
            #pragma unroll
            for (int c = 0; c < 3; c++) {
                float ang = dd[c] * fr;
                s[OFF_B0 + (3 + f * 3 + c) * S + p]  = __sinf(ang);
                s[OFF_B0 + (15 + f * 3 + c) * S + p] = __cosf(ang);
            }
        }
        #pragma unroll
        for (int k = 0; k < 15; k++)
            s[OFF_B0 + (27 + k) * S + p] = s[OFF_B1 + (1 + k) * S + p];
        out[gn] = s[OFF_B1 + 0 * S + p];               // sigma
    }
    __syncthreads();

    // ---- color net ----
    gemmS<42, true>(s + OFF_B0, s + OFF_B1, OFF_CW0, warp, lane);
    __syncthreads();
    gemmS<64, true>(s + OFF_B1, s + OFF_B0, OFF_CW1, warp, lane);
    __syncthreads();

    // ---- final 64 -> 3 + sigmoid ----
    if (tid < BP) {
        const int p = tid;
        const int gn = gbase + p;
        float r0 = 0.f, r1 = 0.f, r2 = 0.f;
        #pragma unroll 8
        for (int i = 0; i < 64; i++) {
            float xv = s[OFF_B0 + i * S + p];
            r0 = fmaf(xv, c_w[OFF_CW2 + i * 3 + 0], r0);
            r1 = fmaf(xv, c_w[OFF_CW2 + i * 3 + 1], r1);
            r2 = fmaf(xv, c_w[OFF_CW2 + i * 3 + 2], r2);
        }
        out[(size_t)NPTS + (size_t)gn * 3 + 0] = 1.f / (1.f + __expf(-r0));
        out[(size_t)NPTS + (size_t)gn * 3 + 1] = 1.f / (1.f + __expf(-r1));
        out[(size_t)NPTS + (size_t)gn * 3 + 2] = 1.f / (1.f + __expf(-r2));
    }
}

// ---------------------------------------------------------------------------
extern "C" void kernel_launch(void* const* d_in, const int* in_sizes, int n_in,
                              void* d_out, int out_size)
{
    const float* xyzt  = (const float*)d_in[0];
    const float* dirs  = (const float*)d_in[1];
    const float* table = (const float*)d_in[2];

    cudaMemcpyToSymbolAsync(c_w, d_in[3], 2048 * 4, OFF_SW0 * 4,
                            cudaMemcpyDeviceToDevice);
    cudaMemcpyToSymbolAsync(c_w, d_in[4], 4096 * 4, OFF_SW1 * 4,
                            cudaMemcpyDeviceToDevice);
    cudaMemcpyToSymbolAsync(c_w, d_in[5], 1024 * 4, OFF_SW2 * 4,
                            cudaMemcpyDeviceToDevice);
    cudaMemcpyToSymbolAsync(c_w, d_in[6], 2688 * 4, OFF_CW0 * 4,
                            cudaMemcpyDeviceToDevice);
    cudaMemcpyToSymbolAsync(c_w, d_in[7], 4096 * 4, OFF_CW1 * 4,
                            cudaMemcpyDeviceToDevice);
    cudaMemcpyToSymbolAsync(c_w, d_in[8], 192 * 4, OFF_CW2 * 4,
                            cudaMemcpyDeviceToDevice);

    cudaFuncSetAttribute(fused_kernel, cudaFuncAttributeMaxDynamicSharedMemorySize,
                         SMEM_BYTES);

    fused_kernel<<<NPTS / BP, NT, SMEM_BYTES>>>(xyzt, dirs, table, (float*)d_out);
}

// round 13
// speedup vs baseline: 2.3084x; 2.3084x over previous
#include <cuda_runtime.h>
#include <math.h>

#define NPTS 262144
#define NLVL 16
#define TSZ  (1u << 19)
#define TMASK (TSZ - 1u)

typedef unsigned long long u64t;

__device__ __forceinline__ u64t pk2(float a, float b) {
    u64t r; asm("mov.b64 %0,{%1,%2};" : "=l"(r) : "f"(a), "f"(b)); return r;
}
__device__ __forceinline__ void upk2(u64t v, float& a, float& b) {
    asm("mov.b64 {%0,%1},%2;" : "=f"(a), "=f"(b) : "l"(v));
}
__device__ __forceinline__ void fma2(u64t& d, u64t a, u64t b) {
    asm("fma.rn.f32x2 %0,%1,%2,%0;" : "+l"(d) : "l"(a), "l"(b));
}

// ---------------------------------------------------------------------------
constexpr int OFF_SW0 = 0;            // 32*64
constexpr int OFF_SW1 = 2048;         // 64*64
constexpr int OFF_SW2 = 6144;         // 64*16
constexpr int OFF_CW0 = 7168;         // 42*64
constexpr int OFF_CW1 = 9856;         // 64*64
constexpr int OFF_CW2 = 13952;        // 64*3
constexpr int W_TOTAL = 14144;
__constant__ float c_w[W_TOTAL];

__constant__ int c_res[NLVL] = {16, 20, 25, 32, 40, 50, 64, 80,
                                101, 128, 161, 203, 256, 322, 406, 512};

constexpr int BP = 128;
constexpr int NT = 512;               // threads per CTA
constexpr int S  = 132;
constexpr int OFF_B0 = 0;
constexpr int OFF_B1 = 64 * S;
constexpr int SMEM_FLOATS = 2 * 64 * S;          // 16896
constexpr int SMEM_BYTES  = SMEM_FLOATS * 4;     // 67584

// ---------------------------------------------------------------------------
// GEMM: y[64][S] = act(W[IN][64]^T x[IN][S]), executed by warps 0..7 only.
// warp -> 8 neurons (4 natural 64-bit cmem pairs) x 128 points, lane -> 4 pts.
// Per iter: 1 LDS.128 (4 wf) + 4 dup movs + 2 LDC.128 + 16 FFMA2.
// Halves layer LDS wavefronts vs the 16-warp/4-neuron form.
// ---------------------------------------------------------------------------
template <int IN, bool RELU>
__device__ __forceinline__ void gemm8(const float* __restrict__ xb,
                                      float* __restrict__ yb,
                                      int woff, int warp, int lane)
{
    u64t acc[4][4];                    // [neuron-pair][point]
    #pragma unroll
    for (int n = 0; n < 4; n++)
        #pragma unroll
        for (int q = 0; q < 4; q++) acc[n][q] = 0ull;

    const float* xr = xb + lane * 4;
    const float* wr = c_w + woff + warp * 8;
    #pragma unroll 4
    for (int i = 0; i < IN; i++) {
        float4 xv = *(const float4*)(xr + i * S);
        u64t x0 = pk2(xv.x, xv.x);
        u64t x1 = pk2(xv.y, xv.y);
        u64t x2 = pk2(xv.z, xv.z);
        u64t x3 = pk2(xv.w, xv.w);
        ulonglong2 wa = *(const ulonglong2*)(wr + i * 64);
        ulonglong2 wb = *(const ulonglong2*)(wr + i * 64 + 4);
        fma2(acc[0][0], x0, wa.x); fma2(acc[0][1], x1, wa.x);
        fma2(acc[0][2], x2, wa.x); fma2(acc[0][3], x3, wa.x);
        fma2(acc[1][0], x0, wa.y); fma2(acc[1][1], x1, wa.y);
        fma2(acc[1][2], x2, wa.y); fma2(acc[1][3], x3, wa.y);
        fma2(acc[2][0], x0, wb.x); fma2(acc[2][1], x1, wb.x);
        fma2(acc[2][2], x2, wb.x); fma2(acc[2][3], x3, wb.x);
        fma2(acc[3][0], x0, wb.y); fma2(acc[3][1], x1, wb.y);
        fma2(acc[3][2], x2, wb.y); fma2(acc[3][3], x3, wb.y);
    }
    #pragma unroll
    for (int n = 0; n < 4; n++) {
        float lo0, hi0, lo1, hi1, lo2, hi2, lo3, hi3;
        upk2(acc[n][0], lo0, hi0);
        upk2(acc[n][1], lo1, hi1);
        upk2(acc[n][2], lo2, hi2);
        upk2(acc[n][3], lo3, hi3);
        if (RELU) {
            lo0 = fmaxf(lo0, 0.f); lo1 = fmaxf(lo1, 0.f);
            lo2 = fmaxf(lo2, 0.f); lo3 = fmaxf(lo3, 0.f);
            hi0 = fmaxf(hi0, 0.f); hi1 = fmaxf(hi1, 0.f);
            hi2 = fmaxf(hi2, 0.f); hi3 = fmaxf(hi3, 0.f);
        }
        *(float4*)(yb + (warp * 8 + 2 * n + 0) * S + lane * 4) =
            make_float4(lo0, lo1, lo2, lo3);
        *(float4*)(yb + (warp * 8 + 2 * n + 1) * S + lane * 4) =
            make_float4(hi0, hi1, hi2, hi3);
    }
}

// sw2 (64 -> 16): warps 0..1, warp -> 8 neurons x 128 points
__device__ __forceinline__ void gemm16_8(const float* __restrict__ xb,
                                         float* __restrict__ yb,
                                         int warp, int lane)
{
    u64t acc[4][4];
    #pragma unroll
    for (int n = 0; n < 4; n++)
        #pragma unroll
        for (int q = 0; q < 4; q++) acc[n][q] = 0ull;

    const float* xr = xb + lane * 4;
    const float* wr = c_w + OFF_SW2 + warp * 8;
    #pragma unroll 4
    for (int i = 0; i < 64; i++) {
        float4 xv = *(const float4*)(xr + i * S);
        u64t x0 = pk2(xv.x, xv.x);
        u64t x1 = pk2(xv.y, xv.y);
        u64t x2 = pk2(xv.z, xv.z);
        u64t x3 = pk2(xv.w, xv.w);
        ulonglong2 wa = *(const ulonglong2*)(wr + i * 16);
        ulonglong2 wb = *(const ulonglong2*)(wr + i * 16 + 4);
        fma2(acc[0][0], x0, wa.x); fma2(acc[0][1], x1, wa.x);
        fma2(acc[0][2], x2, wa.x); fma2(acc[0][3], x3, wa.x);
        fma2(acc[1][0], x0, wa.y); fma2(acc[1][1], x1, wa.y);
        fma2(acc[1][2], x2, wa.y); fma2(acc[1][3], x3, wa.y);
        fma2(acc[2][0], x0, wb.x); fma2(acc[2][1], x1, wb.x);
        fma2(acc[2][2], x2, wb.x); fma2(acc[2][3], x3, wb.x);
        fma2(acc[3][0], x0, wb.y); fma2(acc[3][1], x1, wb.y);
        fma2(acc[3][2], x2, wb.y); fma2(acc[3][3], x3, wb.y);
    }
    #pragma unroll
    for (int n = 0; n < 4; n++) {
        float lo0, hi0, lo1, hi1, lo2, hi2, lo3, hi3;
        upk2(acc[n][0], lo0, hi0);
        upk2(acc[n][1], lo1, hi1);
        upk2(acc[n][2], lo2, hi2);
        upk2(acc[n][3], lo3, hi3);
        *(float4*)(yb + (warp * 8 + 2 * n + 0) * S + lane * 4) =
            make_float4(lo0, lo1, lo2, lo3);
        *(float4*)(yb + (warp * 8 + 2 * n + 1) * S + lane * 4) =
            make_float4(hi0, hi1, hi2, hi3);
    }
}

// ---------------------------------------------------------------------------
// Fused kernel: hash encode (-> smem) then MLPs. 128 points / block, 512 thr.
// ---------------------------------------------------------------------------
__global__ __launch_bounds__(NT, 2) void fused_kernel(
    const float* __restrict__ xyzt,
    const float* __restrict__ dirs,
    const float* __restrict__ table,
    float* __restrict__ out)
{
    extern __shared__ float s[];
    const int tid = threadIdx.x;
    const int warp = tid >> 5, lane = tid & 31;
    const int gbase = blockIdx.x * BP;

    // ---- stage xyzt into B1 (512 floats) ----
    if (tid < 512)
        s[OFF_B1 + tid] = xyzt[(size_t)gbase * 4 + tid];
    __syncthreads();

    // ---- hash phase: 4 threads per point, 4 levels each (R10-validated) ----
    {
        const int p = tid & 127;
        const int lh = tid >> 7;                     // 0..3 (warp-uniform)
        float4 pt = *(const float4*)(s + OFF_B1 + p * 4);

        #pragma unroll 1
        for (int k = 0; k < 4; k++) {
            const int l = 4 * k + lh;
            float r = (float)c_res[l];
            float px = pt.x * r, py = pt.y * r, pz = pt.z * r, pw = pt.w * r;
            float fx = floorf(px), fy = floorf(py), fz = floorf(pz), ft = floorf(pw);
            float wx = px - fx, wy = py - fy, wz = pz - fz, wt = pw - ft;
            unsigned cx = (unsigned)fx, cy = (unsigned)fy,
                     cz = (unsigned)fz, ct = (unsigned)ft;

            unsigned hx0 = cx,               hx1 = cx + 1u;
            unsigned hy0 = cy * 2654435761u, hy1 = (cy + 1u) * 2654435761u;
            unsigned hz0 = cz * 805459861u,  hz1 = (cz + 1u) * 805459861u;
            unsigned ht0 = ct * 3674653429u, ht1 = (ct + 1u) * 3674653429u;

            float wx0 = 1.f - wx, wy0 = 1.f - wy, wz0 = 1.f - wz, wt0 = 1.f - wt;

            const float2* tl = (const float2*)table + (size_t)l * TSZ;
            float a0 = 0.f, a1 = 0.f;

            if ((cx & 1u) == 0u) {
                const float4* t4 = (const float4*)tl;
                #pragma unroll
                for (int c8 = 0; c8 < 8; c8++) {
                    unsigned hyy = (c8 & 1) ? hy1 : hy0;
                    unsigned hzz = (c8 & 2) ? hz1 : hz0;
                    unsigned htt = (c8 & 4) ? ht1 : ht0;
                    unsigned idx0 = (hx0 ^ hyy ^ hzz ^ htt) & TMASK;
                    float wyzt = ((c8 & 1) ? wy : wy0) * ((c8 & 2) ? wz : wz0) *
                                 ((c8 & 4) ? wt : wt0);
                    float w0 = wx0 * wyzt, w1 = wx * wyzt;
                    float4 v = __ldg(&t4[idx0 >> 1]);
                    bool hi = (idx0 & 1u);
                    float f0x = hi ? v.z : v.x, f0y = hi ? v.w : v.y;
                    float f1x = hi ? v.x : v.z, f1y = hi ? v.y : v.w;
                    a0 = fmaf(f0x, w0, a0); a0 = fmaf(f1x, w1, a0);
                    a1 = fmaf(f0y, w0, a1); a1 = fmaf(f1y, w1, a1);
                }
            } else {
                #pragma unroll
                for (int c8 = 0; c8 < 16; c8++) {
                    unsigned hxx = (c8 & 1) ? hx1 : hx0;
                    unsigned hyy = (c8 & 2) ? hy1 : hy0;
                    unsigned hzz = (c8 & 4) ? hz1 : hz0;
                    unsigned htt = (c8 & 8) ? ht1 : ht0;
                    unsigned idx = (hxx ^ hyy ^ hzz ^ htt) & TMASK;
                    float w = ((c8 & 1) ? wx : wx0) * ((c8 & 2) ? wy : wy0) *
                              ((c8 & 4) ? wz : wz0) * ((c8 & 8) ? wt : wt0);
                    float2 f = __ldg(&tl[idx]);
                    a0 = fmaf(f.x, w, a0);
                    a1 = fmaf(f.y, w, a1);
                }
            }
            s[OFF_B0 + (2 * l + 0) * S + p] = a0;
            s[OFF_B0 + (2 * l + 1) * S + p] = a1;
        }
    }
    __syncthreads();

    // ---- sigma net (8 gemm warps) ----
    if (warp < 8) gemm8<32, true>(s + OFF_B0, s + OFF_B1, OFF_SW0, warp, lane);
    __syncthreads();
    if (warp < 8) gemm8<64, true>(s + OFF_B1, s + OFF_B0, OFF_SW1, warp, lane);
    __syncthreads();
    if (warp < 2) gemm16_8(s + OFF_B0, s + OFF_B1, warp, lane);  // h -> B1 0..15
    __syncthreads();

    // ---- color input assembly + sigma output ----
    if (tid < BP) {
        const int p = tid;
        const int gn = gbase + p;
        float d0 = dirs[(size_t)gn * 3 + 0];
        float d1 = dirs[(size_t)gn * 3 + 1];
        float d2 = dirs[(size_t)gn * 3 + 2];
        s[OFF_B0 + 0 * S + p] = d0;
        s[OFF_B0 + 1 * S + p] = d1;
        s[OFF_B0 + 2 * S + p] = d2;
        float dd[3] = {d0, d1, d2};
        #pragma unroll
        for (int f = 0; f < 4; f++) {
            float fr = (float)(1 << f);
            #pragma unroll
            for (int c = 0; c < 3; c++) {
                float ang = dd[c] * fr;
                s[OFF_B0 + (3 + f * 3 + c) * S + p]  = __sinf(ang);
                s[OFF_B0 + (15 + f * 3 + c) * S + p] = __cosf(ang);
            }
        }
        #pragma unroll
        for (int k = 0; k < 15; k++)
            s[OFF_B0 + (27 + k) * S + p] = s[OFF_B1 + (1 + k) * S + p];
        out[gn] = s[OFF_B1 + 0 * S + p];               // sigma
    }
    __syncthreads();

    // ---- color net ----
    if (warp < 8) gemm8<42, true>(s + OFF_B0, s + OFF_B1, OFF_CW0, warp, lane);
    __syncthreads();
    if (warp < 8) gemm8<64, true>(s + OFF_B1, s + OFF_B0, OFF_CW1, warp, lane);
    __syncthreads();

    // ---- final 64 -> 3 + sigmoid ----
    if (tid < BP) {
        const int p = tid;
        const int gn = gbase + p;
        float r0 = 0.f, r1 = 0.f, r2 = 0.f;
        #pragma unroll 8
        for (int i = 0; i < 64; i++) {
            float xv = s[OFF_B0 + i * S + p];
            r0 = fmaf(xv, c_w[OFF_CW2 + i * 3 + 0], r0);
            r1 = fmaf(xv, c_w[OFF_CW2 + i * 3 + 1], r1);
            r2 = fmaf(xv, c_w[OFF_CW2 + i * 3 + 2], r2);
        }
        out[(size_t)NPTS + (size_t)gn * 3 + 0] = 1.f / (1.f + __expf(-r0));
        out[(size_t)NPTS + (size_t)gn * 3 + 1] = 1.f / (1.f + __expf(-r1));
        out[(size_t)NPTS + (size_t)gn * 3 + 2] = 1.f / (1.f + __expf(-r2));
    }
}

// ---------------------------------------------------------------------------
extern "C" void kernel_launch(void* const* d_in, const int* in_sizes, int n_in,
                              void* d_out, int out_size)
{
    const float* xyzt  = (const float*)d_in[0];
    const float* dirs  = (const float*)d_in[1];
    const float* table = (const float*)d_in[2];

    cudaMemcpyToSymbolAsync(c_w, d_in[3], 2048 * 4, OFF_SW0 * 4,
                            cudaMemcpyDeviceToDevice);
    cudaMemcpyToSymbolAsync(c_w, d_in[4], 4096 * 4, OFF_SW1 * 4,
                            cudaMemcpyDeviceToDevice);
    cudaMemcpyToSymbolAsync(c_w, d_in[5], 1024 * 4, OFF_SW2 * 4,
                            cudaMemcpyDeviceToDevice);
    cudaMemcpyToSymbolAsync(c_w, d_in[6], 2688 * 4, OFF_CW0 * 4,
                            cudaMemcpyDeviceToDevice);
    cudaMemcpyToSymbolAsync(c_w, d_in[7], 4096 * 4, OFF_CW1 * 4,
                            cudaMemcpyDeviceToDevice);
    cudaMemcpyToSymbolAsync(c_w, d_in[8], 192 * 4, OFF_CW2 * 4,
                            cudaMemcpyDeviceToDevice);

    cudaFuncSetAttribute(fused_kernel, cudaFuncAttributeMaxDynamicSharedMemorySize,
                         SMEM_BYTES);

    fused_kernel<<<NPTS / BP, NT, SMEM_BYTES>>>(xyzt, dirs, table, (float*)d_out);
}

// round 14
// speedup vs baseline: 2.6176x; 1.1340x over previous
#include <cuda_runtime.h>
#include <math.h>

#define NPTS 262144
#define NLVL 16
#define TSZ  (1u << 19)
#define TMASK (TSZ - 1u)

typedef unsigned long long u64t;

__device__ __forceinline__ u64t pk2(float a, float b) {
    u64t r; asm("mov.b64 %0,{%1,%2};" : "=l"(r) : "f"(a), "f"(b)); return r;
}
__device__ __forceinline__ void upk2(u64t v, float& a, float& b) {
    asm("mov.b64 {%0,%1},%2;" : "=f"(a), "=f"(b) : "l"(v));
}
__device__ __forceinline__ void fma2(u64t& d, u64t a, u64t b) {
    asm("fma.rn.f32x2 %0,%1,%2,%0;" : "+l"(d) : "l"(a), "l"(b));
}

// ---------------------------------------------------------------------------
constexpr int OFF_SW0 = 0;            // 32*64
constexpr int OFF_SW1 = 2048;         // 64*64
constexpr int OFF_SW2 = 6144;         // 64*16
constexpr int OFF_CW0 = 7168;         // 42*64
constexpr int OFF_CW1 = 9856;         // 64*64
constexpr int OFF_CW2 = 13952;        // 64*3
constexpr int W_TOTAL = 14144;
__constant__ float c_w[W_TOTAL];

__constant__ int c_res[NLVL] = {16, 20, 25, 32, 40, 50, 64, 80,
                                101, 128, 161, 203, 256, 322, 406, 512};

constexpr int BP = 128;
constexpr int NT = 512;               // threads per CTA
constexpr int S  = 132;
constexpr int OFF_B0 = 0;
constexpr int OFF_B1 = 64 * S;
constexpr int SMEM_FLOATS = 2 * 64 * S;          // 16896
constexpr int SMEM_BYTES  = SMEM_FLOATS * 4;     // 67584

// ---------------------------------------------------------------------------
// Main GEMM (R10-validated optimum): 16 warps, warp -> 4 neurons,
// lane -> 4 points. Per iter: 1 LDS.128 + 1 LDC.128 + 4 dup movs + 8 FFMA2.
// ---------------------------------------------------------------------------
template <int IN, bool RELU>
__device__ __forceinline__ void gemmC(const float* __restrict__ xb,
                                      float* __restrict__ yb,
                                      int woff, int warp, int lane)
{
    u64t acc[4][2];
    #pragma unroll
    for (int n = 0; n < 4; n++) { acc[n][0] = 0ull; acc[n][1] = 0ull; }

    const float* xr = xb + lane * 4;
    const int wb = woff + warp * 4;
    #pragma unroll 8
    for (int i = 0; i < IN; i++) {
        float4 xv = *(const float4*)(xr + i * S);
        u64t x01 = pk2(xv.x, xv.y);
        u64t x23 = pk2(xv.z, xv.w);
        float4 w = *(const float4*)(c_w + wb + i * 64);
        u64t wd;
        wd = pk2(w.x, w.x); fma2(acc[0][0], x01, wd); fma2(acc[0][1], x23, wd);
        wd = pk2(w.y, w.y); fma2(acc[1][0], x01, wd); fma2(acc[1][1], x23, wd);
        wd = pk2(w.z, w.z); fma2(acc[2][0], x01, wd); fma2(acc[2][1], x23, wd);
        wd = pk2(w.w, w.w); fma2(acc[3][0], x01, wd); fma2(acc[3][1], x23, wd);
    }
    #pragma unroll
    for (int n = 0; n < 4; n++) {
        float a0, a1, a2, a3;
        upk2(acc[n][0], a0, a1);
        upk2(acc[n][1], a2, a3);
        if (RELU) {
            a0 = fmaxf(a0, 0.f); a1 = fmaxf(a1, 0.f);
            a2 = fmaxf(a2, 0.f); a3 = fmaxf(a3, 0.f);
        }
        *(float4*)(yb + (warp * 4 + n) * S + lane * 4) =
            make_float4(a0, a1, a2, a3);
    }
}

// sw2 (64 -> 16), R11-validated mapping: 16 warps = 8 neuron-pairs x 2 point
// halves, lane -> 2 points (LDS.64), natural 64-bit cmem weight pair.
__device__ __forceinline__ void gemm16N(const float* __restrict__ xb,
                                        float* __restrict__ yb,
                                        int warp, int lane)
{
    const int pg = warp >> 3;          // point half
    const int nw = warp & 7;           // neuron pair -> neurons 2nw, 2nw+1
    u64t acc0 = 0ull, acc1 = 0ull;

    const float* xr = xb + pg * 64 + lane * 2;
    const float* wr = c_w + OFF_SW2 + nw * 2;
    #pragma unroll 8
    for (int i = 0; i < 64; i++) {
        float2 xv = *(const float2*)(xr + i * S);
        u64t wp = *(const u64t*)(wr + i * 16);       // natural pair LDC.64
        fma2(acc0, pk2(xv.x, xv.x), wp);
        fma2(acc1, pk2(xv.y, xv.y), wp);
    }
    float lo0, hi0, lo1, hi1;
    upk2(acc0, lo0, hi0);
    upk2(acc1, lo1, hi1);
    *(float2*)(yb + (nw * 2 + 0) * S + pg * 64 + lane * 2) =
        make_float2(lo0, lo1);
    *(float2*)(yb + (nw * 2 + 1) * S + pg * 64 + lane * 2) =
        make_float2(hi0, hi1);
}

// ---------------------------------------------------------------------------
// Fused kernel: hash encode (-> smem) then MLPs. 128 points / block, 512 thr.
// ---------------------------------------------------------------------------
__global__ __launch_bounds__(NT, 2) void fused_kernel(
    const float* __restrict__ xyzt,
    const float* __restrict__ dirs,
    const float* __restrict__ table,
    float* __restrict__ out)
{
    extern __shared__ float s[];
    const int tid = threadIdx.x;
    const int warp = tid >> 5, lane = tid & 31;
    const int gbase = blockIdx.x * BP;

    // ---- stage xyzt into B1 (512 floats) ----
    if (tid < 512)
        s[OFF_B1 + tid] = xyzt[(size_t)gbase * 4 + tid];
    __syncthreads();

    // ---- hash phase: 4 threads per point, 4 levels each (R10-validated) ----
    {
        const int p = tid & 127;
        const int lh = tid >> 7;                     // 0..3 (warp-uniform)
        float4 pt = *(const float4*)(s + OFF_B1 + p * 4);

        #pragma unroll 1
        for (int k = 0; k < 4; k++) {
            const int l = 4 * k + lh;
            float r = (float)c_res[l];
            float px = pt.x * r, py = pt.y * r, pz = pt.z * r, pw = pt.w * r;
            float fx = floorf(px), fy = floorf(py), fz = floorf(pz), ft = floorf(pw);
            float wx = px - fx, wy = py - fy, wz = pz - fz, wt = pw - ft;
            unsigned cx = (unsigned)fx, cy = (unsigned)fy,
                     cz = (unsigned)fz, ct = (unsigned)ft;

            unsigned hx0 = cx,               hx1 = cx + 1u;
            unsigned hy0 = cy * 2654435761u, hy1 = (cy + 1u) * 2654435761u;
            unsigned hz0 = cz * 805459861u,  hz1 = (cz + 1u) * 805459861u;
            unsigned ht0 = ct * 3674653429u, ht1 = (ct + 1u) * 3674653429u;

            float wx0 = 1.f - wx, wy0 = 1.f - wy, wz0 = 1.f - wz, wt0 = 1.f - wt;

            const float2* tl = (const float2*)table + (size_t)l * TSZ;
            float a0 = 0.f, a1 = 0.f;

            if ((cx & 1u) == 0u) {
                const float4* t4 = (const float4*)tl;
                #pragma unroll
                for (int c8 = 0; c8 < 8; c8++) {
                    unsigned hyy = (c8 & 1) ? hy1 : hy0;
                    unsigned hzz = (c8 & 2) ? hz1 : hz0;
                    unsigned htt = (c8 & 4) ? ht1 : ht0;
                    unsigned idx0 = (hx0 ^ hyy ^ hzz ^ htt) & TMASK;
                    float wyzt = ((c8 & 1) ? wy : wy0) * ((c8 & 2) ? wz : wz0) *
                                 ((c8 & 4) ? wt : wt0);
                    float w0 = wx0 * wyzt, w1 = wx * wyzt;
                    float4 v = __ldg(&t4[idx0 >> 1]);
                    bool hi = (idx0 & 1u);
                    float f0x = hi ? v.z : v.x, f0y = hi ? v.w : v.y;
                    float f1x = hi ? v.x : v.z, f1y = hi ? v.y : v.w;
                    a0 = fmaf(f0x, w0, a0); a0 = fmaf(f1x, w1, a0);
                    a1 = fmaf(f0y, w0, a1); a1 = fmaf(f1y, w1, a1);
                }
            } else {
                #pragma unroll
                for (int c8 = 0; c8 < 16; c8++) {
                    unsigned hxx = (c8 & 1) ? hx1 : hx0;
                    unsigned hyy = (c8 & 2) ? hy1 : hy0;
                    unsigned hzz = (c8 & 4) ? hz1 : hz0;
                    unsigned htt = (c8 & 8) ? ht1 : ht0;
                    unsigned idx = (hxx ^ hyy ^ hzz ^ htt) & TMASK;
                    float w = ((c8 & 1) ? wx : wx0) * ((c8 & 2) ? wy : wy0) *
                              ((c8 & 4) ? wz : wz0) * ((c8 & 8) ? wt : wt0);
                    float2 f = __ldg(&tl[idx]);
                    a0 = fmaf(f.x, w, a0);
                    a1 = fmaf(f.y, w, a1);
                }
            }
            s[OFF_B0 + (2 * l + 0) * S + p] = a0;
            s[OFF_B0 + (2 * l + 1) * S + p] = a1;
        }
    }
    __syncthreads();

    // ---- sigma net ----
    gemmC<32, true>(s + OFF_B0, s + OFF_B1, OFF_SW0, warp, lane);
    __syncthreads();
    gemmC<64, true>(s + OFF_B1, s + OFF_B0, OFF_SW1, warp, lane);
    __syncthreads();
    gemm16N(s + OFF_B0, s + OFF_B1, warp, lane);       // h -> B1 rows 0..15
    __syncthreads();

    // ---- color input assembly + sigma output ----
    if (tid < BP) {
        const int p = tid;
        const int gn = gbase + p;
        float d0 = dirs[(size_t)gn * 3 + 0];
        float d1 = dirs[(size_t)gn * 3 + 1];
        float d2 = dirs[(size_t)gn * 3 + 2];
        s[OFF_B0 + 0 * S + p] = d0;
        s[OFF_B0 + 1 * S + p] = d1;
        s[OFF_B0 + 2 * S + p] = d2;
        float dd[3] = {d0, d1, d2};
        #pragma unroll
        for (int f = 0; f < 4; f++) {
            float fr = (float)(1 << f);
            #pragma unroll
            for (int c = 0; c < 3; c++) {
                float ang = dd[c] * fr;
                s[OFF_B0 + (3 + f * 3 + c) * S + p]  = __sinf(ang);
                s[OFF_B0 + (15 + f * 3 + c) * S + p] = __cosf(ang);
            }
        }
        #pragma unroll
        for (int k = 0; k < 15; k++)
            s[OFF_B0 + (27 + k) * S + p] = s[OFF_B1 + (1 + k) * S + p];
        out[gn] = s[OFF_B1 + 0 * S + p];               // sigma
    }
    __syncthreads();

    // ---- color net ----
    gemmC<42, true>(s + OFF_B0, s + OFF_B1, OFF_CW0, warp, lane);
    __syncthreads();
    gemmC<64, true>(s + OFF_B1, s + OFF_B0, OFF_CW1, warp, lane);
    __syncthreads();

    // ---- final 64 -> 3 + sigmoid (batched LDC.128 weight fetch) ----
    if (tid < BP) {
        const int p = tid;
        const int gn = gbase + p;
        float r0 = 0.f, r1 = 0.f, r2 = 0.f;
        #pragma unroll 4
        for (int k = 0; k < 16; k++) {
            // 12 weights = rows 4k..4k+3, fetched as 3x LDC.128
            float4 wa = *(const float4*)(c_w + OFF_CW2 + k * 12);
            float4 wb = *(const float4*)(c_w + OFF_CW2 + k * 12 + 4);
            float4 wc = *(const float4*)(c_w + OFF_CW2 + k * 12 + 8);
            float x0 = s[OFF_B0 + (4 * k + 0) * S + p];
            float x1 = s[OFF_B0 + (4 * k + 1) * S + p];
            float x2 = s[OFF_B0 + (4 * k + 2) * S + p];
            float x3 = s[OFF_B0 + (4 * k + 3) * S + p];
            r0 = fmaf(x0, wa.x, r0); r1 = fmaf(x0, wa.y, r1); r2 = fmaf(x0, wa.z, r2);
            r0 = fmaf(x1, wa.w, r0); r1 = fmaf(x1, wb.x, r1); r2 = fmaf(x1, wb.y, r2);
            r0 = fmaf(x2, wb.z, r0); r1 = fmaf(x2, wb.w, r1); r2 = fmaf(x2, wc.x, r2);
            r0 = fmaf(x3, wc.y, r0); r1 = fmaf(x3, wc.z, r1); r2 = fmaf(x3, wc.w, r2);
        }
        out[(size_t)NPTS + (size_t)gn * 3 + 0] = 1.f / (1.f + __expf(-r0));
        out[(size_t)NPTS + (size_t)gn * 3 + 1] = 1.f / (1.f + __expf(-r1));
        out[(size_t)NPTS + (size_t)gn * 3 + 2] = 1.f / (1.f + __expf(-r2));
    }
}

// ---------------------------------------------------------------------------
extern "C" void kernel_launch(void* const* d_in, const int* in_sizes, int n_in,
                              void* d_out, int out_size)
{
    const float* xyzt  = (const float*)d_in[0];
    const float* dirs  = (const float*)d_in[1];
    const float* table = (const float*)d_in[2];

    cudaMemcpyToSymbolAsync(c_w, d_in[3], 2048 * 4, OFF_SW0 * 4,
                            cudaMemcpyDeviceToDevice);
    cudaMemcpyToSymbolAsync(c_w, d_in[4], 4096 * 4, OFF_SW1 * 4,
                            cudaMemcpyDeviceToDevice);
    cudaMemcpyToSymbolAsync(c_w, d_in[5], 1024 * 4, OFF_SW2 * 4,
                            cudaMemcpyDeviceToDevice);
    cudaMemcpyToSymbolAsync(c_w, d_in[6], 2688 * 4, OFF_CW0 * 4,
                            cudaMemcpyDeviceToDevice);
    cudaMemcpyToSymbolAsync(c_w, d_in[7], 4096 * 4, OFF_CW1 * 4,
                            cudaMemcpyDeviceToDevice);
    cudaMemcpyToSymbolAsync(c_w, d_in[8], 192 * 4, OFF_CW2 * 4,
                            cudaMemcpyDeviceToDevice);

    cudaFuncSetAttribute(fused_kernel, cudaFuncAttributeMaxDynamicSharedMemorySize,
                         SMEM_BYTES);

    fused_kernel<<<NPTS / BP, NT, SMEM_BYTES>>>(xyzt, dirs, table, (float*)d_out);
}

// round 15
// speedup vs baseline: 2.6368x; 1.0073x over previous
#include <cuda_runtime.h>
#include <math.h>

#define NPTS 262144
#define NLVL 16
#define TSZ  (1u << 19)
#define TMASK (TSZ - 1u)

typedef unsigned long long u64t;

__device__ __forceinline__ u64t pk2(float a, float b) {
    u64t r; asm("mov.b64 %0,{%1,%2};" : "=l"(r) : "f"(a), "f"(b)); return r;
}
__device__ __forceinline__ void upk2(u64t v, float& a, float& b) {
    asm("mov.b64 {%0,%1},%2;" : "=f"(a), "=f"(b) : "l"(v));
}
__device__ __forceinline__ void fma2(u64t& d, u64t a, u64t b) {
    asm("fma.rn.f32x2 %0,%1,%2,%0;" : "+l"(d) : "l"(a), "l"(b));
}

// ---------------------------------------------------------------------------
constexpr int OFF_SW0 = 0;            // 32*64
constexpr int OFF_SW1 = 2048;         // 64*64
constexpr int OFF_SW2 = 6144;         // 64*16
constexpr int OFF_CW0 = 7168;         // 42*64
constexpr int OFF_CW1 = 9856;         // 64*64
constexpr int OFF_CW2 = 13952;        // 64*3
constexpr int W_TOTAL = 14144;
__constant__ float c_w[W_TOTAL];

__constant__ int c_res[NLVL] = {16, 20, 25, 32, 40, 50, 64, 80,
                                101, 128, 161, 203, 256, 322, 406, 512};

constexpr int BP = 128;
constexpr int NT = 512;               // threads per CTA
constexpr int S  = 132;
constexpr int OFF_B0 = 0;
constexpr int OFF_B1 = 64 * S;
constexpr int ROW_SIGMA = 50;         // spare B1 row for sigma (h neuron 0)
constexpr int SMEM_FLOATS = 2 * 64 * S;          // 16896
constexpr int SMEM_BYTES  = SMEM_FLOATS * 4;     // 67584

// ---------------------------------------------------------------------------
// Main GEMM (R10-validated optimum): 16 warps, warp -> 4 neurons,
// lane -> 4 points. Per iter: 1 LDS.128 + 1 LDC.128 + 4 dup movs + 8 FFMA2.
// ---------------------------------------------------------------------------
template <int IN, bool RELU>
__device__ __forceinline__ void gemmC(const float* __restrict__ xb,
                                      float* __restrict__ yb,
                                      int woff, int warp, int lane)
{
    u64t acc[4][2];
    #pragma unroll
    for (int n = 0; n < 4; n++) { acc[n][0] = 0ull; acc[n][1] = 0ull; }

    const float* xr = xb + lane * 4;
    const int wb = woff + warp * 4;
    #pragma unroll 8
    for (int i = 0; i < IN; i++) {
        float4 xv = *(const float4*)(xr + i * S);
        u64t x01 = pk2(xv.x, xv.y);
        u64t x23 = pk2(xv.z, xv.w);
        float4 w = *(const float4*)(c_w + wb + i * 64);
        u64t wd;
        wd = pk2(w.x, w.x); fma2(acc[0][0], x01, wd); fma2(acc[0][1], x23, wd);
        wd = pk2(w.y, w.y); fma2(acc[1][0], x01, wd); fma2(acc[1][1], x23, wd);
        wd = pk2(w.z, w.z); fma2(acc[2][0], x01, wd); fma2(acc[2][1], x23, wd);
        wd = pk2(w.w, w.w); fma2(acc[3][0], x01, wd); fma2(acc[3][1], x23, wd);
    }
    #pragma unroll
    for (int n = 0; n < 4; n++) {
        float a0, a1, a2, a3;
        upk2(acc[n][0], a0, a1);
        upk2(acc[n][1], a2, a3);
        if (RELU) {
            a0 = fmaxf(a0, 0.f); a1 = fmaxf(a1, 0.f);
            a2 = fmaxf(a2, 0.f); a3 = fmaxf(a3, 0.f);
        }
        *(float4*)(yb + (warp * 4 + n) * S + lane * 4) =
            make_float4(a0, a1, a2, a3);
    }
}

// sw2 (64 -> 16) on warps 0..7: warp -> neurons (2w, 2w+1) via natural
// LDC.64 pair, lane -> 4 points. Writes h DIRECTLY into color-input rows:
// neuron 0 -> B1 row ROW_SIGMA, neuron n>=1 -> B1 row 26+n.
__device__ __forceinline__ void gemm16D(const float* __restrict__ xb,
                                        float* __restrict__ yb,
                                        int warp, int lane)
{
    u64t acc[4];                       // acc[point] = {neuron 2w, neuron 2w+1}
    #pragma unroll
    for (int q = 0; q < 4; q++) acc[q] = 0ull;

    const float* xr = xb + lane * 4;
    const float* wr = c_w + OFF_SW2 + warp * 2;
    #pragma unroll 8
    for (int i = 0; i < 64; i++) {
        float4 xv = *(const float4*)(xr + i * S);
        u64t wp = *(const u64t*)(wr + i * 16);       // natural pair LDC.64
        fma2(acc[0], pk2(xv.x, xv.x), wp);
        fma2(acc[1], pk2(xv.y, xv.y), wp);
        fma2(acc[2], pk2(xv.z, xv.z), wp);
        fma2(acc[3], pk2(xv.w, xv.w), wp);
    }
    float lo0, hi0, lo1, hi1, lo2, hi2, lo3, hi3;
    upk2(acc[0], lo0, hi0);
    upk2(acc[1], lo1, hi1);
    upk2(acc[2], lo2, hi2);
    upk2(acc[3], lo3, hi3);
    const int n0 = 2 * warp, n1 = 2 * warp + 1;
    const int r0 = (n0 == 0) ? ROW_SIGMA : 26 + n0;
    const int r1 = 26 + n1;
    *(float4*)(yb + r0 * S + lane * 4) = make_float4(lo0, lo1, lo2, lo3);
    *(float4*)(yb + r1 * S + lane * 4) = make_float4(hi0, hi1, hi2, hi3);
}

// ---------------------------------------------------------------------------
// Fused kernel: hash encode (-> smem) then MLPs. 128 points / block, 512 thr.
// ---------------------------------------------------------------------------
__global__ __launch_bounds__(NT, 2) void fused_kernel(
    const float* __restrict__ xyzt,
    const float* __restrict__ dirs,
    const float* __restrict__ table,
    float* __restrict__ out)
{
    extern __shared__ float s[];
    const int tid = threadIdx.x;
    const int warp = tid >> 5, lane = tid & 31;
    const int gbase = blockIdx.x * BP;

    // ---- stage xyzt into B1 (512 floats) ----
    s[OFF_B1 + tid] = xyzt[(size_t)gbase * 4 + tid];
    __syncthreads();

    // ---- hash phase: 4 threads per point, 4 levels each (R10-validated) ----
    {
        const int p = tid & 127;
        const int lh = tid >> 7;                     // 0..3 (warp-uniform)
        float4 pt = *(const float4*)(s + OFF_B1 + p * 4);

        #pragma unroll 1
        for (int k = 0; k < 4; k++) {
            const int l = 4 * k + lh;
            float r = (float)c_res[l];
            float px = pt.x * r, py = pt.y * r, pz = pt.z * r, pw = pt.w * r;
            float fx = floorf(px), fy = floorf(py), fz = floorf(pz), ft = floorf(pw);
            float wx = px - fx, wy = py - fy, wz = pz - fz, wt = pw - ft;
            unsigned cx = (unsigned)fx, cy = (unsigned)fy,
                     cz = (unsigned)fz, ct = (unsigned)ft;

            unsigned hx0 = cx,               hx1 = cx + 1u;
            unsigned hy0 = cy * 2654435761u, hy1 = (cy + 1u) * 2654435761u;
            unsigned hz0 = cz * 805459861u,  hz1 = (cz + 1u) * 805459861u;
            unsigned ht0 = ct * 3674653429u, ht1 = (ct + 1u) * 3674653429u;

            float wx0 = 1.f - wx, wy0 = 1.f - wy, wz0 = 1.f - wz, wt0 = 1.f - wt;

            const float2* tl = (const float2*)table + (size_t)l * TSZ;
            float a0 = 0.f, a1 = 0.f;

            if ((cx & 1u) == 0u) {
                const float4* t4 = (const float4*)tl;
                #pragma unroll
                for (int c8 = 0; c8 < 8; c8++) {
                    unsigned hyy = (c8 & 1) ? hy1 : hy0;
                    unsigned hzz = (c8 & 2) ? hz1 : hz0;
                    unsigned htt = (c8 & 4) ? ht1 : ht0;
                    unsigned idx0 = (hx0 ^ hyy ^ hzz ^ htt) & TMASK;
                    float wyzt = ((c8 & 1) ? wy : wy0) * ((c8 & 2) ? wz : wz0) *
                                 ((c8 & 4) ? wt : wt0);
                    float w0 = wx0 * wyzt, w1 = wx * wyzt;
                    float4 v = __ldg(&t4[idx0 >> 1]);
                    bool hi = (idx0 & 1u);
                    float f0x = hi ? v.z : v.x, f0y = hi ? v.w : v.y;
                    float f1x = hi ? v.x : v.z, f1y = hi ? v.y : v.w;
                    a0 = fmaf(f0x, w0, a0); a0 = fmaf(f1x, w1, a0);
                    a1 = fmaf(f0y, w0, a1); a1 = fmaf(f1y, w1, a1);
                }
            } else {
                #pragma unroll
                for (int c8 = 0; c8 < 16; c8++) {
                    unsigned hxx = (c8 & 1) ? hx1 : hx0;
                    unsigned hyy = (c8 & 2) ? hy1 : hy0;
                    unsigned hzz = (c8 & 4) ? hz1 : hz0;
                    unsigned htt = (c8 & 8) ? ht1 : ht0;
                    unsigned idx = (hxx ^ hyy ^ hzz ^ htt) & TMASK;
                    float w = ((c8 & 1) ? wx : wx0) * ((c8 & 2) ? wy : wy0) *
                              ((c8 & 4) ? wz : wz0) * ((c8 & 8) ? wt : wt0);
                    float2 f = __ldg(&tl[idx]);
                    a0 = fmaf(f.x, w, a0);
                    a1 = fmaf(f.y, w, a1);
                }
            }
            s[OFF_B0 + (2 * l + 0) * S + p] = a0;
            s[OFF_B0 + (2 * l + 1) * S + p] = a1;
        }
    }
    __syncthreads();

    // ---- sigma net layers 1-2 ----
    gemmC<32, true>(s + OFF_B0, s + OFF_B1, OFF_SW0, warp, lane);
    __syncthreads();
    gemmC<64, true>(s + OFF_B1, s + OFF_B0, OFF_SW1, warp, lane);
    __syncthreads();

    // ---- merged phase: warps 0-7 gemm16 (h -> B1 rows 27..41 + ROW_SIGMA),
    //      warps 8-15 freq-encode assembly (-> B1 rows 0..26) ----
    if (warp < 8) {
        gemm16D(s + OFF_B0, s + OFF_B1, warp, lane);
    } else {
        const int local = tid - 256;
        const int p = local & 127;
        const int h = local >> 7;                 // 0 or 1
        const int gn = gbase + p;
        float d0 = dirs[(size_t)gn * 3 + 0];
        float d1 = dirs[(size_t)gn * 3 + 1];
        float d2 = dirs[(size_t)gn * 3 + 2];
        float dd[3] = {d0, d1, d2};
        if (h == 0) {
            s[OFF_B1 + 0 * S + p] = d0;
            s[OFF_B1 + 1 * S + p] = d1;
            s[OFF_B1 + 2 * S + p] = d2;
            #pragma unroll
            for (int f = 0; f < 2; f++) {
                float fr = (float)(1 << f);
                #pragma unroll
                for (int c = 0; c < 3; c++) {
                    float ang = dd[c] * fr;
                    s[OFF_B1 + (3 + f * 3 + c) * S + p]  = __sinf(ang);
                    s[OFF_B1 + (15 + f * 3 + c) * S + p] = __cosf(ang);
                }
            }
        } else {
            #pragma unroll
            for (int f = 2; f < 4; f++) {
                float fr = (float)(1 << f);
                #pragma unroll
                for (int c = 0; c < 3; c++) {
                    float ang = dd[c] * fr;
                    s[OFF_B1 + (3 + f * 3 + c) * S + p]  = __sinf(ang);
                    s[OFF_B1 + (15 + f * 3 + c) * S + p] = __cosf(ang);
                }
            }
        }
    }
    __syncthreads();

    // ---- sigma output (reads B1 ROW_SIGMA; no conflict with gemm<42>) ----
    if (tid < BP)
        out[gbase + tid] = s[OFF_B1 + ROW_SIGMA * S + tid];

    // ---- color net: B1 -> B0 -> B1 ----
    gemmC<42, true>(s + OFF_B1, s + OFF_B0, OFF_CW0, warp, lane);
    __syncthreads();
    gemmC<64, true>(s + OFF_B0, s + OFF_B1, OFF_CW1, warp, lane);
    __syncthreads();

    // ---- final 64 -> 3 + sigmoid (batched LDC.128 weight fetch) ----
    if (tid < BP) {
        const int p = tid;
        const int gn = gbase + p;
        float r0 = 0.f, r1 = 0.f, r2 = 0.f;
        #pragma unroll 4
        for (int k = 0; k < 16; k++) {
            float4 wa = *(const float4*)(c_w + OFF_CW2 + k * 12);
            float4 wb = *(const float4*)(c_w + OFF_CW2 + k * 12 + 4);
            float4 wc = *(const float4*)(c_w + OFF_CW2 + k * 12 + 8);
            float x0 = s[OFF_B1 + (4 * k + 0) * S + p];
            float x1 = s[OFF_B1 + (4 * k + 1) * S + p];
            float x2 = s[OFF_B1 + (4 * k + 2) * S + p];
            float x3 = s[OFF_B1 + (4 * k + 3) * S + p];
            r0 = fmaf(x0, wa.x, r0); r1 = fmaf(x0, wa.y, r1); r2 = fmaf(x0, wa.z, r2);
            r0 = fmaf(x1, wa.w, r0); r1 = fmaf(x1, wb.x, r1); r2 = fmaf(x1, wb.y, r2);
            r0 = fmaf(x2, wb.z, r0); r1 = fmaf(x2, wb.w, r1); r2 = fmaf(x2, wc.x, r2);
            r0 = fmaf(x3, wc.y, r0); r1 = fmaf(x3, wc.z, r1); r2 = fmaf(x3, wc.w, r2);
        }
        out[(size_t)NPTS + (size_t)gn * 3 + 0] = 1.f / (1.f + __expf(-r0));
        out[(size_t)NPTS + (size_t)gn * 3 + 1] = 1.f / (1.f + __expf(-r1));
        out[(size_t)NPTS + (size_t)gn * 3 + 2] = 1.f / (1.f + __expf(-r2));
    }
}

// ---------------------------------------------------------------------------
extern "C" void kernel_launch(void* const* d_in, const int* in_sizes, int n_in,
                              void* d_out, int out_size)
{
    const float* xyzt  = (const float*)d_in[0];
    const float* dirs  = (const float*)d_in[1];
    const float* table = (const float*)d_in[2];

    cudaMemcpyToSymbolAsync(c_w, d_in[3], 2048 * 4, OFF_SW0 * 4,
                            cudaMemcpyDeviceToDevice);
    cudaMemcpyToSymbolAsync(c_w, d_in[4], 4096 * 4, OFF_SW1 * 4,
                            cudaMemcpyDeviceToDevice);
    cudaMemcpyToSymbolAsync(c_w, d_in[5], 1024 * 4, OFF_SW2 * 4,
                            cudaMemcpyDeviceToDevice);
    cudaMemcpyToSymbolAsync(c_w, d_in[6], 2688 * 4, OFF_CW0 * 4,
                            cudaMemcpyDeviceToDevice);
    cudaMemcpyToSymbolAsync(c_w, d_in[7], 4096 * 4, OFF_CW1 * 4,
                            cudaMemcpyDeviceToDevice);
    cudaMemcpyToSymbolAsync(c_w, d_in[8], 192 * 4, OFF_CW2 * 4,
                            cudaMemcpyDeviceToDevice);

    cudaFuncSetAttribute(fused_kernel, cudaFuncAttributeMaxDynamicSharedMemorySize,
                         SMEM_BYTES);

    fused_kernel<<<NPTS / BP, NT, SMEM_BYTES>>>(xyzt, dirs, table, (float*)d_out);
}